// round 12
// baseline (speedup 1.0000x reference)
#include <cuda_runtime.h>

// Problem sizes (fixed by the dataset)
#define BB 8
#define LL 2048
#define DD 128
#define CC 64              // chunks per batch
#define LC 32              // events per chunk (LL / CC)
#define EPSC 1e-6f

// Chunk-local decayed embedding sums (referenced at each chunk's last time).
__device__ float    g_T[BB * CC * DD];     // 256 KB
// Per-batch monotone barrier tickets, padded to one 128B line each.
// Never reset: each launch adds 64 per batch; target = next multiple of 64.
__device__ unsigned g_cnt[BB * 32];

// ---------------------------------------------------------------------------
// Fused kernel, 256 threads per chunk (lane owns 2 dims -> 2x warps/SM vs
// the 128-thread version; all D-parallel loops halve per-warp work).
// Warp-pair p (threads p*64..p*64+63) owns events p*8..p*8+7.
//
//  1. E gather at instr 0 (id broadcast -> LDG.128), overlapped precompute.
//  2. T matvec -> g_T ; fence ; ARRIVE (per-batch ticket).
//  3. Pre-barrier in-chunk work: pair z-sums, factorized scan without the
//     carry A (chunk-constant, folded later): pp[i][tp] = e_i,tp . H.
//  4. WAIT (tid0 spin + syncthreads).
//  5. Carry A = sum_{c2<c} cw(c2) T[b,c2] (pairs split 16 chunks each,
//     predicated); fold e_i . A into pp; 8-thread/event reduce; parallel
//     logs; one atomicAdd per chunk.
// ---------------------------------------------------------------------------
__global__ void __launch_bounds__(256) hawkes_fused(
    const int*   __restrict__ ids,
    const float* __restrict__ times,
    const float* __restrict__ mask,
    const float* __restrict__ emb,
    const float* __restrict__ u_table,
    const float* __restrict__ beta_p,
    float*       __restrict__ out)
{
    __shared__ float4 s_E4[LC * 32];        // 16 KB: 32 rows x 128 floats
    __shared__ float2 s_part2[4 * 64];      // T partials
    __shared__ float2 s_zsum2[4 * 64];      // per-pair z sums
    __shared__ float2 s_carry2[4 * 64];     // per-pair carry partials
    __shared__ float  s_pp[LC][65];         // per-thread dot partials (padded)
    __shared__ float  s_cw[CC];
    __shared__ float  s_sw[LC], s_w[LC], s_v[LC], s_bu[LC];
    __shared__ float  s_r[LC];

    const int tid  = threadIdx.x;
    const int wp   = tid >> 6;             // warp-pair 0..3
    const int tp   = tid & 63;             // thread-in-pair
    const int g    = blockIdx.x;           // b*CC + c
    const int b    = g >> 6;
    const int c    = g & (CC - 1);
    const int base = b * LL + c * LC;

    // ---- 1. E gather at instruction 0 (float4 granularity) ----
    const float4* embv = (const float4*)emb;
    float4 ebuf[4];
#pragma unroll
    for (int it = 0; it < 4; ++it) {
        int idx = it * 256 + tid;          // idx = row*32 + f4
        int row = idx >> 5, f4 = idx & 31;
        int id  = __ldg(&ids[base + row]);
        ebuf[it] = embv[(size_t)id * 32 + f4];
    }

    // ---- Overlapped precompute ----
    const float beta  = beta_p[0];
    const float t0    = times[base];
    const float tlast = times[base + LC - 1];

    if (c == 0 && tid == 0) out[b] = 0.f;  // fenced before arrive below

    if (tid < LC) {
        float t  = times[base + tid];
        float m  = mask[base + tid];
        int   id = ids[base + tid];
        s_sw[tid] = m * __expf(beta * (t - tlast));   // T weight
        s_w [tid] = m * __expf(beta * (t - t0));      // z weight
        s_v [tid] = __expf(-beta * (t - t0));         // re-reference factor
        s_bu[tid] = beta * u_table[id];
    } else if (tid < 32 + CC) {
        int c2 = tid - 32;
        float wgt = 0.f;
        if (c2 < c) {
            float tref = times[b * LL + c2 * LC + LC - 1];
            wgt = __expf(-beta * (t0 - tref));
        }
        s_cw[c2] = wgt;
    }

#pragma unroll
    for (int it = 0; it < 4; ++it) s_E4[it * 256 + tid] = ebuf[it];
    __syncthreads();

    const float2* E2 = (const float2*)s_E4;      // row i at E2[i*64]

    // ---- 2. T matvec (pair p sums its 8 events) -> g_T; ARRIVE ----
    {
        float2 a = {0.f, 0.f};
#pragma unroll
        for (int k = 0; k < 8; ++k) {
            int j = wp * 8 + k;
            float swt = s_sw[j];
            float2 e = E2[j * 64 + tp];
            a.x += swt * e.x; a.y += swt * e.y;
        }
        s_part2[wp * 64 + tp] = a;
    }
    __syncthreads();
    if (tid < 64) {
        float2 a0 = s_part2[tid],       a1 = s_part2[64 + tid];
        float2 a2 = s_part2[128 + tid], a3 = s_part2[192 + tid];
        float2 T;
        T.x = (a0.x + a1.x) + (a2.x + a3.x);
        T.y = (a0.y + a1.y) + (a2.y + a3.y);
        ((float2*)g_T)[g * 64 + tid] = T;
    }
    __syncthreads();
    __threadfence();                        // release g_T (and out[b]=0)
    unsigned target = 0;
    if (tid == 0) {
        unsigned t = atomicAdd(&g_cnt[b * 32], 1u);
        target = ((t >> 6) + 1u) << 6;      // next multiple of 64
    }

    // ---- 3. Pre-barrier: z-sums then in-chunk scan (A excluded) ----
    {
        float2 zz = {0.f, 0.f};
#pragma unroll
        for (int k = 0; k < 8; ++k) {
            int j = wp * 8 + k;
            float wz = s_w[j];
            float2 e = E2[j * 64 + tp];
            zz.x += wz * e.x; zz.y += wz * e.y;
        }
        s_zsum2[wp * 64 + tp] = zz;
    }
    __syncthreads();
    {
        float2 H = {0.f, 0.f};
#pragma unroll
        for (int p = 0; p < 3; ++p) {
            if (p < wp) {
                float2 z = s_zsum2[p * 64 + tp];
                H.x += z.x; H.y += z.y;
            }
        }
#pragma unroll
        for (int k = 0; k < 8; ++k) {
            int i = wp * 8 + k;
            float2 e = E2[i * 64 + tp];
            s_pp[i][tp] = e.x * H.x + e.y * H.y;
            float wz = s_w[i];
            H.x += wz * e.x; H.y += wz * e.y;
        }
    }

    // ---- 4. WAIT ----
    if (tid == 0) {
        unsigned cur;
        for (;;) {
            asm volatile("ld.global.acquire.gpu.u32 %0, [%1];"
                         : "=r"(cur) : "l"(&g_cnt[b * 32]));
            if (cur >= target) break;
            __nanosleep(64);
        }
    }
    __syncthreads();

    // ---- 5a. Carry partials: pair wp handles 16 chunks (predicated) ----
    const float2* Tb2 = (const float2*)g_T + (b * CC) * 64;
    {
        float2 A0 = {0,0}, A1 = {0,0}, A2_ = {0,0}, A3 = {0,0};
        const int c2b = wp * 16;
#pragma unroll
        for (int k = 0; k < 16; k += 4) {
            float w0 = s_cw[c2b + k],     w1 = s_cw[c2b + k + 1];
            float w2 = s_cw[c2b + k + 2], w3 = s_cw[c2b + k + 3];
            if (w0 != 0.f) { float2 T = Tb2[(c2b + k    ) * 64 + tp];
                A0.x += w0*T.x; A0.y += w0*T.y; }
            if (w1 != 0.f) { float2 T = Tb2[(c2b + k + 1) * 64 + tp];
                A1.x += w1*T.x; A1.y += w1*T.y; }
            if (w2 != 0.f) { float2 T = Tb2[(c2b + k + 2) * 64 + tp];
                A2_.x += w2*T.x; A2_.y += w2*T.y; }
            if (w3 != 0.f) { float2 T = Tb2[(c2b + k + 3) * 64 + tp];
                A3.x += w3*T.x; A3.y += w3*T.y; }
        }
        float2 P;
        P.x = (A0.x + A1.x) + (A2_.x + A3.x);
        P.y = (A0.y + A1.y) + (A2_.y + A3.y);
        s_carry2[wp * 64 + tp] = P;
    }
    __syncthreads();

    // ---- 5b. Fold e_i . A into pp (A chunk-constant) ----
    {
        float2 p0 = s_carry2[tp],       p1 = s_carry2[64 + tp];
        float2 p2 = s_carry2[128 + tp], p3 = s_carry2[192 + tp];
        float2 A;
        A.x = (p0.x + p1.x) + (p2.x + p3.x);
        A.y = (p0.y + p1.y) + (p2.y + p3.y);
#pragma unroll
        for (int k = 0; k < 8; ++k) {
            int i = wp * 8 + k;
            float2 e = E2[i * 64 + tp];
            s_pp[i][tp] += e.x * A.x + e.y * A.y;
        }
    }
    __syncthreads();

    // ---- 5c. 8 threads per event reduce its 64 partials ----
    {
        int e = tid >> 3, q = tid & 7;
        float s = 0.f;
#pragma unroll
        for (int k = 0; k < 8; ++k) s += s_pp[e][q * 8 + k];
        s += __shfl_xor_sync(0xffffffffu, s, 1);
        s += __shfl_xor_sync(0xffffffffu, s, 2);
        s += __shfl_xor_sync(0xffffffffu, s, 4);
        if (q == 0) {
            float lam = s_bu[e] * s_v[e] * s;
            s_r[e] = __logf(lam + EPSC);
        }
    }
    __syncthreads();

    if (tid < 32) {
        float lg = s_r[tid];
        lg += __shfl_xor_sync(0xffffffffu, lg, 16);
        lg += __shfl_xor_sync(0xffffffffu, lg, 8);
        lg += __shfl_xor_sync(0xffffffffu, lg, 4);
        lg += __shfl_xor_sync(0xffffffffu, lg, 2);
        lg += __shfl_xor_sync(0xffffffffu, lg, 1);
        if (tid == 0) atomicAdd(&out[b], lg);
    }
}

// ---------------------------------------------------------------------------
extern "C" void kernel_launch(void* const* d_in, const int* in_sizes, int n_in,
                              void* d_out, int out_size)
{
    const int*   ids   = (const int*)d_in[0];
    const float* times = (const float*)d_in[1];
    const float* mask  = (const float*)d_in[2];
    const float* emb   = (const float*)d_in[3];
    const float* u_tab = (const float*)d_in[4];
    const float* beta  = (const float*)d_in[5];
    float* out = (float*)d_out;

    hawkes_fused<<<BB * CC, 256>>>(ids, times, mask, emb, u_tab, beta, out);
}

// round 13
// speedup vs baseline: 1.1925x; 1.1925x over previous
#include <cuda_runtime.h>

// Problem sizes (fixed by the dataset)
#define BB 8
#define LL 2048
#define DD 128
#define CC 64              // chunks per batch
#define LC 32              // events per chunk (LL / CC)
#define EPSC 1e-6f

// Chunk z-sums T'[b,c,:] = sum_{j in c} m_j e_j exp(beta*(t_j - t_mid_b)),
// anchored at the batch midpoint time (exponents bounded by ~±12.5).
__device__ float    g_T[BB * CC * DD];     // 256 KB
// Per-batch monotone barrier tickets, padded to one 128B line each.
// Never reset: each launch adds 64 per batch; target = next multiple of 64.
__device__ unsigned g_cnt[BB * 32];

// ---------------------------------------------------------------------------
// Fused kernel, 128 threads per chunk (best measured shape), global-anchor
// factorization:  exp(-beta(t_i - t_j)) = v_i * w_j,
//   w_j = m_j exp(beta(t_j - ta)),  v_i = exp(-beta(t_i - ta)),  ta = batch mid.
// Then lam_i = beta u_i v_i * ( e_i . (A_c + H_i) ) with
//   A_c = sum_{c2<c} T'_{c2}        (UNWEIGHTED prefix -> trivial carry)
//   H_i = sum_{j<i, j in c} w_j e_j (in-chunk scan)
// and T'_c is exactly the chunk z-sum, so phase 1 and the z-sum are ONE pass.
// ---------------------------------------------------------------------------
__global__ void __launch_bounds__(128) hawkes_fused(
    const int*   __restrict__ ids,
    const float* __restrict__ times,
    const float* __restrict__ mask,
    const float* __restrict__ emb,
    const float* __restrict__ u_table,
    const float* __restrict__ beta_p,
    float*       __restrict__ out)
{
    __shared__ float4 s_E4[LC * 32];       // 16 KB: 32 rows x 32 float4
    __shared__ float4 s_zsum[128];         // per-warp z partials
    __shared__ float4 s_carry[128];        // per-warp carry partials
    __shared__ float  s_pp[LC][33];        // padded per-lane dot partials
    __shared__ float  s_w[LC], s_v[LC], s_bu[LC];
    __shared__ float  s_r[LC];

    const int tid  = threadIdx.x;
    const int w    = tid >> 5;
    const int lane = tid & 31;
    const int g    = blockIdx.x;           // b*CC + c
    const int b    = g >> 6;
    const int c    = g & (CC - 1);
    const int base = b * LL + c * LC;

    // ---- E gather at instruction 0 (id broadcast -> coalesced LDG.128) ----
    const float4* embv = (const float4*)emb;
    float4 ebuf[8];
#pragma unroll
    for (int it = 0; it < 8; ++it) {
        int idx = it * 128 + tid;          // idx = row*32 + f4
        int row = idx >> 5, f4 = idx & 31;
        int id  = __ldg(&ids[base + row]);
        ebuf[it] = embv[(size_t)id * 32 + f4];
    }

    // ---- Overlapped precompute (batch-anchored factors) ----
    const float beta = beta_p[0];
    const float ta   = times[b * LL + LL / 2];   // same for all chunks of b

    if (c == 0 && tid == 0) out[b] = 0.f;  // released by the fence below

    if (tid < LC) {
        float t  = times[base + tid];
        float m  = mask[base + tid];
        int   id = ids[base + tid];
        s_w [tid] = m * __expf(beta * (t - ta));   // |exponent| <= ~12.5
        s_v [tid] = __expf(-beta * (t - ta));
        s_bu[tid] = beta * u_table[id];
    }

#pragma unroll
    for (int it = 0; it < 8; ++it) s_E4[it * 128 + tid] = ebuf[it];
    __syncthreads();

    // ---- Phase 1: per-warp z-sums (this IS the T' matvec) ----
    {
        float4 zz = {0.f, 0.f, 0.f, 0.f};
#pragma unroll
        for (int k = 0; k < 8; ++k) {
            int j = w * 8 + k;
            float wz = s_w[j];
            float4 e = s_E4[j * 32 + lane];
            zz.x += wz * e.x; zz.y += wz * e.y; zz.z += wz * e.z; zz.w += wz * e.w;
        }
        s_zsum[w * 32 + lane] = zz;
    }
    __syncthreads();
    if (tid < 32) {
        float4 a0 = s_zsum[tid],      a1 = s_zsum[32 + tid];
        float4 a2 = s_zsum[64 + tid], a3 = s_zsum[96 + tid];
        float4 T;
        T.x = (a0.x + a1.x) + (a2.x + a3.x);
        T.y = (a0.y + a1.y) + (a2.y + a3.y);
        T.z = (a0.z + a1.z) + (a2.z + a3.z);
        T.w = (a0.w + a1.w) + (a2.w + a3.w);
        ((float4*)g_T)[g * 32 + tid] = T;
    }
    __syncthreads();
    __threadfence();                        // release g_T (and out[b]=0)
    unsigned target = 0;
    if (tid == 0) {
        unsigned t = atomicAdd(&g_cnt[b * 32], 1u);
        target = ((t >> 6) + 1u) << 6;      // next multiple of 64
    }

    // ---- Pre-barrier: in-chunk scan (carry A folded in later) ----
    {
        float4 H = {0.f, 0.f, 0.f, 0.f};
#pragma unroll
        for (int p = 0; p < 3; ++p) {
            if (p < w) {
                float4 z = s_zsum[p * 32 + lane];
                H.x += z.x; H.y += z.y; H.z += z.z; H.w += z.w;
            }
        }
#pragma unroll
        for (int k = 0; k < 8; ++k) {
            int i = w * 8 + k;
            float4 e = s_E4[i * 32 + lane];
            s_pp[i][lane] = e.x * H.x + e.y * H.y + e.z * H.z + e.w * H.w;
            float wz = s_w[i];
            H.x += wz * e.x; H.y += wz * e.y; H.z += wz * e.z; H.w += wz * e.w;
        }
    }

    // ---- WAIT ----
    if (tid == 0) {
        unsigned cur;
        for (;;) {
            asm volatile("ld.global.acquire.gpu.u32 %0, [%1];"
                         : "=r"(cur) : "l"(&g_cnt[b * 32]));
            if (cur >= target) break;
            __nanosleep(64);
        }
    }
    __syncthreads();

    // ---- Carry: UNWEIGHTED prefix of T', 16 chunks per warp, predicated ----
    const float4* Tb = (const float4*)g_T + (b * CC) * 32;
    {
        float4 A0 = {0,0,0,0}, A1 = {0,0,0,0}, A2 = {0,0,0,0}, A3 = {0,0,0,0};
        const int c2b = w * 16;
#pragma unroll
        for (int k = 0; k < 16; k += 4) {
            if (c2b + k     < c) { float4 T = Tb[(c2b + k    ) * 32 + lane];
                A0.x += T.x; A0.y += T.y; A0.z += T.z; A0.w += T.w; }
            if (c2b + k + 1 < c) { float4 T = Tb[(c2b + k + 1) * 32 + lane];
                A1.x += T.x; A1.y += T.y; A1.z += T.z; A1.w += T.w; }
            if (c2b + k + 2 < c) { float4 T = Tb[(c2b + k + 2) * 32 + lane];
                A2.x += T.x; A2.y += T.y; A2.z += T.z; A2.w += T.w; }
            if (c2b + k + 3 < c) { float4 T = Tb[(c2b + k + 3) * 32 + lane];
                A3.x += T.x; A3.y += T.y; A3.z += T.z; A3.w += T.w; }
        }
        float4 P;
        P.x = (A0.x + A1.x) + (A2.x + A3.x);
        P.y = (A0.y + A1.y) + (A2.y + A3.y);
        P.z = (A0.z + A1.z) + (A2.z + A3.z);
        P.w = (A0.w + A1.w) + (A2.w + A3.w);
        s_carry[w * 32 + lane] = P;
    }
    __syncthreads();

    // ---- Fold e_i . A into pp (A chunk-constant) ----
    {
        float4 p0 = s_carry[lane],      p1 = s_carry[32 + lane];
        float4 p2 = s_carry[64 + lane], p3 = s_carry[96 + lane];
        float4 A;
        A.x = (p0.x + p1.x) + (p2.x + p3.x);
        A.y = (p0.y + p1.y) + (p2.y + p3.y);
        A.z = (p0.z + p1.z) + (p2.z + p3.z);
        A.w = (p0.w + p1.w) + (p2.w + p3.w);
#pragma unroll
        for (int k = 0; k < 8; ++k) {
            int i = w * 8 + k;
            float4 e = s_E4[i * 32 + lane];
            s_pp[i][lane] += e.x * A.x + e.y * A.y + e.z * A.z + e.w * A.w;
        }
    }
    __syncthreads();

    // ---- 4 threads per event reduce its 32 lane-partials; parallel logs ----
    {
        int e = tid >> 2, q = tid & 3;
        float s = 0.f;
#pragma unroll
        for (int k = 0; k < 8; ++k) s += s_pp[e][q * 8 + k];   // conflict-free
        s += __shfl_xor_sync(0xffffffffu, s, 1);
        s += __shfl_xor_sync(0xffffffffu, s, 2);
        if (q == 0) {
            float lam = s_bu[e] * s_v[e] * s;
            s_r[e] = __logf(lam + EPSC);
        }
    }
    __syncthreads();

    if (w == 0) {
        float lg = s_r[lane];
        lg += __shfl_xor_sync(0xffffffffu, lg, 16);
        lg += __shfl_xor_sync(0xffffffffu, lg, 8);
        lg += __shfl_xor_sync(0xffffffffu, lg, 4);
        lg += __shfl_xor_sync(0xffffffffu, lg, 2);
        lg += __shfl_xor_sync(0xffffffffu, lg, 1);
        if (lane == 0) atomicAdd(&out[b], lg);
    }
}

// ---------------------------------------------------------------------------
extern "C" void kernel_launch(void* const* d_in, const int* in_sizes, int n_in,
                              void* d_out, int out_size)
{
    const int*   ids   = (const int*)d_in[0];
    const float* times = (const float*)d_in[1];
    const float* mask  = (const float*)d_in[2];
    const float* emb   = (const float*)d_in[3];
    const float* u_tab = (const float*)d_in[4];
    const float* beta  = (const float*)d_in[5];
    float* out = (float*)d_out;

    hawkes_fused<<<BB * CC, 128>>>(ids, times, mask, emb, u_tab, beta, out);
}